// round 7
// baseline (speedup 1.0000x reference)
#include <cuda_runtime.h>
#include <cstdint>

// ---------------------------------------------------------------------------
// GatingNetwork: logits = x @ W^T + b ; softmax ; top-2 (values, indices)
// Int8 tensor-core path: mma.sync.m16n8k32.s8 with exact base-256 2-digit
// fixed point. Xv=round(4096 x)=256 x1+x2, Wv=round(SW w)=256 w1+w2.
// logit = (65536*S(x1w1) + 256*S(x1w2+x2w1)) / (4096*SW)   [x2w2 dropped]
// Cross term in ONE IMMA pair via A=[w2|w1] / B=[x1|x2] half-K packing.
// Error sigma ~6e-5 -> ambiguous top-3 (gap<6e-4) recomputed exactly (fixup).
// ---------------------------------------------------------------------------

#define HIDDEN   4096
#define NEXP     64
#define NTOK     16384
#define MTILE    128
#define NCTA     (NTOK / MTILE)        // 128
#define THREADS  256
#define NSTEP    (HIDDEN / 32)         // 128 k32-steps
#define STEPS_PER_CHUNK 8              // K=256 per chunk
#define NCHUNK   (NSTEP / STEPS_PER_CHUNK)  // 16
#define GAP_THR  6e-4f

#define SWF      2064384.0f            // 63 * 2^15; |w*SWF| < 32256
#define INV_S    (1.0 / (4096.0 * 2064384.0))

// per k32-step: 4 mblocks x 3 images (hi, cr1, cr2) x 32 lanes x uint4
#define FRAG_PER_STEP   (4 * 3 * 32)           // 384 uint4 = 6144 B
#define CHUNK_BYTES     (STEPS_PER_CHUNK * FRAG_PER_STEP * 16)  // 49152
#define SMEM_TOTAL      (3 * CHUNK_BYTES)      // 147456

__device__ uint4 g_Wfrag[NSTEP * FRAG_PER_STEP];   // 768 KB
__device__ int   g_flag_count;
__device__ int   g_flag_tokens[NTOK];

static __device__ __forceinline__ uint32_t s2u(const void* p) {
    uint32_t a;
    asm("{ .reg .u64 t; cvta.to.shared.u64 t, %1; cvt.u32.u64 %0, t; }" : "=r"(a) : "l"(p));
    return a;
}

#define IMMA(D, A, B0, B1)                                                    \
    asm volatile(                                                             \
        "mma.sync.aligned.m16n8k32.row.col.s32.s8.s8.s32 "                    \
        "{%0,%1,%2,%3},{%4,%5,%6,%7},{%8,%9},{%0,%1,%2,%3};"                  \
        : "+r"((D)[0]), "+r"((D)[1]), "+r"((D)[2]), "+r"((D)[3])              \
        : "r"((A)[0]), "r"((A)[1]), "r"((A)[2]), "r"((A)[3]), "r"(B0), "r"(B1))

#define LDS128(R, addr)                                                       \
    asm volatile("ld.shared.v4.b32 {%0,%1,%2,%3}, [%4];"                      \
                 : "=r"((R)[0]), "=r"((R)[1]), "=r"((R)[2]), "=r"((R)[3])     \
                 : "r"(addr))

static __device__ __forceinline__ void cp16(uint32_t sdst, const void* gsrc) {
    asm volatile("cp.async.cg.shared.global [%0], [%1], 16;"
                 :: "r"(sdst), "l"(gsrc) : "memory");
}

// float4 -> packed hi-digit bytes (x1) and lo-digit bytes (x2)
static __device__ __forceinline__ void xdigits(float4 f, uint32_t& x1, uint32_t& x2) {
    int i0 = __float2int_rn(f.x * 4096.0f);
    int i1 = __float2int_rn(f.y * 4096.0f);
    int i2 = __float2int_rn(f.z * 4096.0f);
    int i3 = __float2int_rn(f.w * 4096.0f);
    int j0 = i0 + 128, j1 = i1 + 128, j2 = i2 + 128, j3 = i3 + 128;
    // x1 bytes = byte1 of (i+128)  (== (v+128)>>8 low byte)
    uint32_t a = __byte_perm(j0, j1, 0x0051);
    uint32_t b = __byte_perm(j2, j3, 0x0051);
    x1 = __byte_perm(a, b, 0x5410);
    // x2 bytes = byte0 of i (two's complement low digit)
    uint32_t c = __byte_perm(i0, i1, 0x0040);
    uint32_t d = __byte_perm(i2, i3, 0x0040);
    x2 = __byte_perm(c, d, 0x5410);
}

// ---------------------------------------------------------------------------
// Prep: W digits packed into IMMA A-fragment images. idx = ((t*4+mb)*3+img)*32+l.
//   img0 (hi) : {w1 r0 ka, w1 r1 ka, w1 r0 kb, w1 r1 kb}
//   img1 (cr1): {w2 r0 ka, w2 r1 ka, w1 r0 ka, w1 r1 ka}
//   img2 (cr2): {w2 r0 kb, w2 r1 kb, w1 r0 kb, w1 r1 kb}
// ---------------------------------------------------------------------------
static __device__ __forceinline__ void wdigits(const float* __restrict__ W,
                                               int row, int k0,
                                               uint32_t& p1, uint32_t& p2) {
    p1 = 0; p2 = 0;
#pragma unroll
    for (int j = 0; j < 4; j++) {
        int v = __float2int_rn(W[(size_t)row * HIDDEN + k0 + j] * SWF);
        int v1 = (v + 128) >> 8;
        int v2 = v - (v1 << 8);
        p1 |= (uint32_t)(v1 & 0xFF) << (8 * j);
        p2 |= (uint32_t)(v2 & 0xFF) << (8 * j);
    }
}

__global__ void prep_w_kernel(const float* __restrict__ W) {
    int idx = blockIdx.x * blockDim.x + threadIdx.x;
    if (idx == 0) g_flag_count = 0;
    if (idx >= NSTEP * FRAG_PER_STEP) return;
    int l = idx & 31;
    int r = idx >> 5;
    int img = r % 3;  r /= 3;
    int mb = r & 3;
    int t = r >> 2;

    int q = l & 3;
    int row0 = mb * 16 + (l >> 2);
    int row1 = row0 + 8;
    int ka = t * 32 + 4 * q;
    int kb = ka + 16;

    uint32_t h0a, l0a, h1a, l1a, h0b, l0b, h1b, l1b;
    wdigits(W, row0, ka, h0a, l0a);
    wdigits(W, row1, ka, h1a, l1a);
    wdigits(W, row0, kb, h0b, l0b);
    wdigits(W, row1, kb, h1b, l1b);

    uint4 v;
    if (img == 0)      { v.x = h0a; v.y = h1a; v.z = h0b; v.w = h1b; }
    else if (img == 1) { v.x = l0a; v.y = l1a; v.z = h0a; v.w = h1a; }
    else               { v.x = l0b; v.y = l1b; v.z = h0b; v.w = h1b; }
    g_Wfrag[idx] = v;
}

// ---------------------------------------------------------------------------
// Main kernel: 8 warps; warp w owns tokens [blk*128 + w*16, +16) x 64 experts.
// ---------------------------------------------------------------------------
__global__ __launch_bounds__(THREADS, 1)
void gating_kernel(const float* __restrict__ x,
                   const float* __restrict__ bias,
                   float* __restrict__ out) {
    extern __shared__ char smem[];
    const uint32_t sb = s2u(smem);
    const int tid = threadIdx.x;
    const int w   = tid >> 5;
    const int l   = tid & 31;
    const int q   = l & 3;

    auto issue_chunk = [&](int ch) {
        const char* gsrc = (const char*)g_Wfrag + (size_t)ch * CHUNK_BYTES;
        uint32_t sdst = sb + (ch % 3) * CHUNK_BYTES;
#pragma unroll
        for (int i = 0; i < CHUNK_BYTES / 16 / THREADS; i++) {
            int off = (tid + i * THREADS) * 16;
            cp16(sdst + off, gsrc + off);
        }
        asm volatile("cp.async.commit_group;" ::: "memory");
    };

    issue_chunk(0);
    issue_chunk(1);

    // lane's x row: token tbase + l/4 (g=1: +8 rows); k base = 4q (+16)
    const int tbase = blockIdx.x * MTILE + w * 16;
    const float* p0 = x + (size_t)(tbase + (l >> 2)) * HIDDEN + 4 * q;
    const float* p1 = p0 + (size_t)8 * HIDDEN;

    // x pipeline, depth 2: [slot][g][half] float4
    float4 vx[2][2][2];
#pragma unroll
    for (int d = 0; d < 2; d++) {
        vx[d][0][0] = *(const float4*)(p0 + d * 32);
        vx[d][0][1] = *(const float4*)(p0 + d * 32 + 16);
        vx[d][1][0] = *(const float4*)(p1 + d * 32);
        vx[d][1][1] = *(const float4*)(p1 + d * 32 + 16);
    }

    int Dhi[4][2][4], Dcr[4][2][4];
#pragma unroll
    for (int mb = 0; mb < 4; mb++)
#pragma unroll
        for (int g = 0; g < 2; g++)
#pragma unroll
            for (int i = 0; i < 4; i++) { Dhi[mb][g][i] = 0; Dcr[mb][g][i] = 0; }

#pragma unroll 1
    for (int t = 0; t < NSTEP; t++) {
        if ((t & (STEPS_PER_CHUNK - 1)) == 0) {
            const int ch = t / STEPS_PER_CHUNK;
            if (ch < NCHUNK - 1)
                asm volatile("cp.async.wait_group 1;" ::: "memory");
            else
                asm volatile("cp.async.wait_group 0;" ::: "memory");
            __syncthreads();
            if (ch + 2 < NCHUNK) issue_chunk(ch + 2);
        }

        const int slot = t & 1;

        // ---- B digit fragments: X1/X2 for both halves, both token groups ----
        uint32_t X1a[2], X2a[2], X1b[2], X2b[2];
#pragma unroll
        for (int g = 0; g < 2; g++) {
            xdigits(vx[slot][g][0], X1a[g], X2a[g]);
            xdigits(vx[slot][g][1], X1b[g], X2b[g]);
        }

        // ---- prefetch x for step t+2 into this slot ----
        if (t + 2 < NSTEP) {
            const float* q0 = p0 + (size_t)(t + 2) * 32;
            const float* q1 = p1 + (size_t)(t + 2) * 32;
            vx[slot][0][0] = *(const float4*)(q0);
            vx[slot][0][1] = *(const float4*)(q0 + 16);
            vx[slot][1][0] = *(const float4*)(q1);
            vx[slot][1][1] = *(const float4*)(q1 + 16);
        }

        // ---- 24 IMMA: per mb {hi, cr1, cr2} x {g0, g1} ----
        const uint32_t base = sb + ((t / STEPS_PER_CHUNK) % 3) * CHUNK_BYTES
                              + (t & (STEPS_PER_CHUNK - 1)) * (FRAG_PER_STEP * 16)
                              + l * 16;
#pragma unroll
        for (int mb = 0; mb < 4; mb++) {
            uint32_t Ahi[4], Ac1[4], Ac2[4];
            const uint32_t mbase = base + mb * 1536;
            LDS128(Ahi, mbase);
            LDS128(Ac1, mbase + 512);
            LDS128(Ac2, mbase + 1024);
            IMMA(Dhi[mb][0], Ahi, X1a[0], X1b[0]);
            IMMA(Dhi[mb][1], Ahi, X1a[1], X1b[1]);
            IMMA(Dcr[mb][0], Ac1, X1a[0], X2a[0]);
            IMMA(Dcr[mb][1], Ac1, X1a[1], X2a[1]);
            IMMA(Dcr[mb][0], Ac2, X1b[0], X2b[0]);
            IMMA(Dcr[mb][1], Ac2, X1b[1], X2b[1]);
        }
    }

    // All warps done reading the smem ring before slog overwrites it.
    __syncthreads();

    // ---- epilogue: combine digits, stage logits in smem ----
    float* slog = (float*)smem;   // pitch 65 floats per token
#pragma unroll
    for (int mb = 0; mb < 4; mb++) {
        int e0 = mb * 16 + (l >> 2);
        int e1 = e0 + 8;
#pragma unroll
        for (int g = 0; g < 2; g++) {
            int tk = w * 16 + g * 8 + 2 * q;
            float v0 = (float)(((double)Dhi[mb][g][0] * 65536.0 + (double)Dcr[mb][g][0] * 256.0) * INV_S);
            float v1 = (float)(((double)Dhi[mb][g][1] * 65536.0 + (double)Dcr[mb][g][1] * 256.0) * INV_S);
            float v2 = (float)(((double)Dhi[mb][g][2] * 65536.0 + (double)Dcr[mb][g][2] * 256.0) * INV_S);
            float v3 = (float)(((double)Dhi[mb][g][3] * 65536.0 + (double)Dcr[mb][g][3] * 256.0) * INV_S);
            slog[(size_t)tk * 65 + e0]       = v0;
            slog[(size_t)(tk + 1) * 65 + e0] = v1;
            slog[(size_t)tk * 65 + e1]       = v2;
            slog[(size_t)(tk + 1) * 65 + e1] = v3;
        }
    }
    __syncthreads();

    if (tid < MTILE) {
        const float* row = slog + (size_t)tid * 65;
        float m1 = -3.4e38f, m2 = -3.4e38f, m3 = -3.4e38f;
        int i1 = 0, i2 = 0;
        float lg[NEXP];
#pragma unroll
        for (int e = 0; e < NEXP; e++) {
            float vv = row[e] + bias[e];
            lg[e] = vv;
            if (vv > m1)      { m3 = m2; m2 = m1; i2 = i1; m1 = vv; i1 = e; }
            else if (vv > m2) { m3 = m2; m2 = vv; i2 = e; }
            else if (vv > m3) { m3 = vv; }
        }
        float s = 0.0f;
#pragma unroll
        for (int e = 0; e < NEXP; e++) s += __expf(lg[e] - m1);

        const float v1 = 1.0f / s;
        const float v2 = __expf(m2 - m1) * v1;
        const int token = blockIdx.x * MTILE + tid;
        ((float2*)out)[token] = make_float2(v1, v2);
        ((float2*)(out + 2 * NTOK))[token] = make_float2((float)i1, (float)i2);

        if ((m1 - m2) < GAP_THR || (m2 - m3) < GAP_THR) {
            int slot = atomicAdd(&g_flag_count, 1);
            if (slot < NTOK) g_flag_tokens[slot] = token;
        }
    }
}

// ---------------------------------------------------------------------------
// Fixup: exact fp32 recompute of flagged tokens (warp-per-8-experts, shuffle
// reduction; W stays L2-hot).
// ---------------------------------------------------------------------------
__global__ __launch_bounds__(256, 1)
void fixup_kernel(const float* __restrict__ x,
                  const float* __restrict__ W,
                  const float* __restrict__ bias,
                  float* __restrict__ out) {
    __shared__ float xs[HIDDEN];
    __shared__ float lg[NEXP];
    const int tid = threadIdx.x;
    const int w = tid >> 5, l = tid & 31;
    const int cnt = min(g_flag_count, NTOK);

    for (int i = blockIdx.x; i < cnt; i += gridDim.x) {
        const int tok = g_flag_tokens[i];
        __syncthreads();
        for (int j = tid; j < HIDDEN / 4; j += 256)
            ((float4*)xs)[j] = ((const float4*)(x + (size_t)tok * HIDDEN))[j];
        __syncthreads();

#pragma unroll
        for (int e8 = 0; e8 < 8; e8++) {
            const int e = w * 8 + e8;
            const float* wr = W + (size_t)e * HIDDEN;
            float s = 0.0f;
#pragma unroll 8
            for (int k = l * 4; k < HIDDEN; k += 128) {
                float4 a = *(const float4*)(xs + k);
                float4 bb = *(const float4*)(wr + k);
                s += a.x * bb.x + a.y * bb.y + a.z * bb.z + a.w * bb.w;
            }
#pragma unroll
            for (int o = 16; o; o >>= 1) s += __shfl_xor_sync(0xFFFFFFFFu, s, o);
            if (l == 0) lg[e] = s + bias[e];
        }
        __syncthreads();

        if (tid == 0) {
            float m1 = -3.4e38f, m2 = -3.4e38f;
            int i1 = 0, i2 = 0;
            for (int ee = 0; ee < NEXP; ee++) {
                float vv = lg[ee];
                if (vv > m1)      { m2 = m1; i2 = i1; m1 = vv; i1 = ee; }
                else if (vv > m2) { m2 = vv; i2 = ee; }
            }
            float ssum = 0.0f;
            for (int ee = 0; ee < NEXP; ee++) ssum += __expf(lg[ee] - m1);
            const float v1 = 1.0f / ssum;
            const float v2 = __expf(m2 - m1) * v1;
            ((float2*)out)[tok] = make_float2(v1, v2);
            ((float2*)(out + 2 * NTOK))[tok] = make_float2((float)i1, (float)i2);
        }
    }
}

// ---------------------------------------------------------------------------
extern "C" void kernel_launch(void* const* d_in, const int* in_sizes, int n_in,
                              void* d_out, int out_size) {
    const float* x = (const float*)d_in[0];
    const float* W = (const float*)d_in[1];
    const float* b = (const float*)d_in[2];
    float* out = (float*)d_out;

    cudaFuncSetAttribute(gating_kernel, cudaFuncAttributeMaxDynamicSharedMemorySize,
                         SMEM_TOTAL);

    prep_w_kernel<<<(NSTEP * FRAG_PER_STEP + 255) / 256, 256>>>(W);
    gating_kernel<<<NCTA, THREADS, SMEM_TOTAL>>>(x, b, out);
    fixup_kernel<<<128, 256>>>(x, W, b, out);
}

// round 8
// speedup vs baseline: 1.7046x; 1.7046x over previous
#include <cuda_runtime.h>
#include <cuda_bf16.h>
#include <cstdint>

// ---------------------------------------------------------------------------
// GatingNetwork: logits = x @ W^T + b ; softmax ; top-2 (values, indices)
// 2-way bf16 split of both operands, 3 partial products (HH+HM+MH) on
// mma.sync m16n8k16 -> logit abs error ~3e-7. Ambiguous top-3 orderings
// (gap < 1e-5) recomputed exactly in fp32 by a parallel fixup kernel.
// k-loop unrolled by 2: 48 HMMA per warp per iteration (96/SMSP) so the
// per-iteration serial overhead (LDS->cvt->MMA chain) stays hidden.
// ---------------------------------------------------------------------------

#define HIDDEN   4096
#define NEXP     64
#define NTOK     16384
#define MTILE    128
#define NCTA     (NTOK / MTILE)        // 128
#define THREADS  256
#define NSTEP    (HIDDEN / 16)         // 256 k16-steps
#define NITER    (NSTEP / 2)           // 128 k32-iterations
#define STEPS_PER_CHUNK 8              // K=128 per W chunk
#define ITERS_PER_CHUNK 4
#define NCHUNK   (NSTEP / STEPS_PER_CHUNK)  // 32
#define GAP_THR  1e-5f

// W fragment image: per k16 step: 4 mblocks x 2 splits x 32 lanes x uint4
#define FRAG_PER_STEP   (4 * 2 * 32)           // 256 uint4 = 4 KB
#define CHUNK_BYTES     (STEPS_PER_CHUNK * FRAG_PER_STEP * 16)  // 32768
#define SMEM_TOTAL      (3 * CHUNK_BYTES)      // 98304

__device__ uint4 g_Wfrag[NSTEP * FRAG_PER_STEP];   // 1 MB
__device__ int   g_flag_count;
__device__ int   g_flag_tokens[NTOK];

static __device__ __forceinline__ uint32_t s2u(const void* p) {
    uint32_t a;
    asm("{ .reg .u64 t; cvta.to.shared.u64 t, %1; cvt.u32.u64 %0, t; }" : "=r"(a) : "l"(p));
    return a;
}

// pack bf16x2: hi = bf16(f_odd), lo = bf16(f_even)
static __device__ __forceinline__ uint32_t pack2(float f_even, float f_odd) {
    uint32_t r;
    asm("cvt.rn.bf16x2.f32 %0, %1, %2;" : "=r"(r) : "f"(f_odd), "f"(f_even));
    return r;
}

#define MMA(D, A, B0, B1)                                                     \
    asm volatile(                                                             \
        "mma.sync.aligned.m16n8k16.row.col.f32.bf16.bf16.f32 "                \
        "{%0,%1,%2,%3},{%4,%5,%6,%7},{%8,%9},{%0,%1,%2,%3};"                  \
        : "+f"((D)[0]), "+f"((D)[1]), "+f"((D)[2]), "+f"((D)[3])              \
        : "r"((A)[0]), "r"((A)[1]), "r"((A)[2]), "r"((A)[3]), "r"(B0), "r"(B1))

#define LDS128(R, addr)                                                       \
    asm volatile("ld.shared.v4.b32 {%0,%1,%2,%3}, [%4];"                      \
                 : "=r"((R)[0]), "=r"((R)[1]), "=r"((R)[2]), "=r"((R)[3])     \
                 : "r"(addr))

static __device__ __forceinline__ void cp16(uint32_t sdst, const void* gsrc) {
    asm volatile("cp.async.cg.shared.global [%0], [%1], 16;"
                 :: "r"(sdst), "l"(gsrc) : "memory");
}

// ---------------------------------------------------------------------------
// Prep: split W into bf16 hi/mid and pack into mma A-fragment order.
// Index: ((t*4 + mb)*2 + s)*32 + lane, one uint4 each. Also zeroes flags.
// ---------------------------------------------------------------------------
static __device__ __forceinline__ float split_res(float f, int s) {
    for (int i = 0; i < s; i++)
        f -= __bfloat162float(__float2bfloat16_rn(f));
    return f;
}

__global__ void prep_w_kernel(const float* __restrict__ W) {
    int idx = blockIdx.x * blockDim.x + threadIdx.x;
    if (idx == 0) g_flag_count = 0;
    if (idx >= NSTEP * FRAG_PER_STEP) return;
    int l = idx & 31;
    int r = idx >> 5;
    int s = r & 1;  r >>= 1;
    int mb = r & 3;
    int t = r >> 2;

    int q = l & 3;
    int row0 = mb * 16 + (l >> 2);
    int row1 = row0 + 8;
    int c = t * 16 + 2 * q;

    const float* w0 = W + (size_t)row0 * HIDDEN + c;
    const float* w1 = W + (size_t)row1 * HIDDEN + c;

    uint4 v;
    v.x = pack2(split_res(w0[0], s), split_res(w0[1], s));
    v.y = pack2(split_res(w1[0], s), split_res(w1[1], s));
    v.z = pack2(split_res(w0[8], s), split_res(w0[9], s));
    v.w = pack2(split_res(w1[8], s), split_res(w1[9], s));
    g_Wfrag[idx] = v;
}

// ---------------------------------------------------------------------------
// Main kernel: 8 warps; warp w owns tokens [blk*128 + w*16, +16) x 64 experts.
// One iteration = 2 k16-steps = 48 HMMA per warp.
// ---------------------------------------------------------------------------
__global__ __launch_bounds__(THREADS, 1)
void gating_kernel(const float* __restrict__ x,
                   const float* __restrict__ bias,
                   float* __restrict__ out) {
    extern __shared__ char smem[];
    const uint32_t sb = s2u(smem);
    const int tid = threadIdx.x;
    const int w   = tid >> 5;
    const int l   = tid & 31;
    const int q   = l & 3;

    auto issue_chunk = [&](int ch) {
        const char* gsrc = (const char*)g_Wfrag + (size_t)ch * CHUNK_BYTES;
        uint32_t sdst = sb + (ch % 3) * CHUNK_BYTES;
#pragma unroll
        for (int i = 0; i < CHUNK_BYTES / 16 / THREADS; i++) {
            int off = (tid + i * THREADS) * 16;
            cp16(sdst + off, gsrc + off);
        }
        asm volatile("cp.async.commit_group;" ::: "memory");
    };

    issue_chunk(0);
    issue_chunk(1);

    const int tbase = blockIdx.x * MTILE + w * 16;
    const float* p0 = x + (size_t)(tbase + (l >> 2)) * HIDDEN + 2 * q;
    const float* p1 = p0 + (size_t)8 * HIDDEN;

    // x pipeline: [slot][substep][g][half] float2 ; one iter consumes 8 float2
    float2 vx[2][2][2][2];
#pragma unroll
    for (int d = 0; d < 2; d++)
#pragma unroll
        for (int su = 0; su < 2; su++) {
            const float* q0 = p0 + (size_t)(2 * d + su) * 16;
            const float* q1 = p1 + (size_t)(2 * d + su) * 16;
            vx[d][su][0][0] = *(const float2*)(q0);
            vx[d][su][0][1] = *(const float2*)(q0 + 8);
            vx[d][su][1][0] = *(const float2*)(q1);
            vx[d][su][1][1] = *(const float2*)(q1 + 8);
        }

    float D[4][2][4];
#pragma unroll
    for (int mb = 0; mb < 4; mb++)
#pragma unroll
        for (int g = 0; g < 2; g++)
#pragma unroll
            for (int i = 0; i < 4; i++) D[mb][g][i] = 0.0f;

#pragma unroll 1
    for (int it = 0; it < NITER; it++) {
        if ((it & (ITERS_PER_CHUNK - 1)) == 0) {
            const int ch = it / ITERS_PER_CHUNK;
            if (ch < NCHUNK - 1)
                asm volatile("cp.async.wait_group 1;" ::: "memory");
            else
                asm volatile("cp.async.wait_group 0;" ::: "memory");
            __syncthreads();
            if (ch + 2 < NCHUNK) issue_chunk(ch + 2);
        }

        const int slot = it & 1;

        // ---- B fragments for both substeps: Bs[substep][split][g][half] ----
        uint32_t Bs[2][2][2][2];
#pragma unroll
        for (int su = 0; su < 2; su++)
#pragma unroll
            for (int g = 0; g < 2; g++)
#pragma unroll
                for (int h = 0; h < 2; h++) {
                    float f0 = vx[slot][su][g][h].x, f1 = vx[slot][su][g][h].y;
                    uint32_t H = pack2(f0, f1);
                    float h0 = __uint_as_float(H << 16);
                    float h1 = __uint_as_float(H & 0xFFFF0000u);
                    uint32_t M = pack2(f0 - h0, f1 - h1);
                    Bs[su][0][g][h] = H; Bs[su][1][g][h] = M;
                }

        // ---- prefetch x for iteration it+2 into this slot ----
        if (it + 2 < NITER) {
#pragma unroll
            for (int su = 0; su < 2; su++) {
                const float* q0 = p0 + (size_t)(2 * (it + 2) + su) * 16;
                const float* q1 = p1 + (size_t)(2 * (it + 2) + su) * 16;
                vx[slot][su][0][0] = *(const float2*)(q0);
                vx[slot][su][0][1] = *(const float2*)(q0 + 8);
                vx[slot][su][1][0] = *(const float2*)(q1);
                vx[slot][su][1][1] = *(const float2*)(q1 + 8);
            }
        }

        // ---- 48 MMA: 4 mblocks x 2 substeps x {HxH, HxM, MxH} x {g0, g1} ----
        const int t2 = 2 * it;
        const uint32_t base = sb + ((t2 / STEPS_PER_CHUNK) % 3) * CHUNK_BYTES
                              + (t2 & (STEPS_PER_CHUNK - 1)) * (FRAG_PER_STEP * 16)
                              + l * 16;
#pragma unroll
        for (int mb = 0; mb < 4; mb++) {
            const uint32_t mbase = base + mb * 1024;
            uint32_t AH0[4], AM0[4], AH1[4], AM1[4];
            LDS128(AH0, mbase);
            LDS128(AM0, mbase + 512);
            LDS128(AH1, mbase + FRAG_PER_STEP * 16);
            LDS128(AM1, mbase + FRAG_PER_STEP * 16 + 512);
            MMA(D[mb][0], AH0, Bs[0][0][0][0], Bs[0][0][0][1]);   // s0 HxH g0
            MMA(D[mb][1], AH0, Bs[0][0][1][0], Bs[0][0][1][1]);   // s0 HxH g1
            MMA(D[mb][0], AH0, Bs[0][1][0][0], Bs[0][1][0][1]);   // s0 HxM g0
            MMA(D[mb][1], AH0, Bs[0][1][1][0], Bs[0][1][1][1]);   // s0 HxM g1
            MMA(D[mb][0], AM0, Bs[0][0][0][0], Bs[0][0][0][1]);   // s0 MxH g0
            MMA(D[mb][1], AM0, Bs[0][0][1][0], Bs[0][0][1][1]);   // s0 MxH g1
            MMA(D[mb][0], AH1, Bs[1][0][0][0], Bs[1][0][0][1]);   // s1 HxH g0
            MMA(D[mb][1], AH1, Bs[1][0][1][0], Bs[1][0][1][1]);   // s1 HxH g1
            MMA(D[mb][0], AH1, Bs[1][1][0][0], Bs[1][1][0][1]);   // s1 HxM g0
            MMA(D[mb][1], AH1, Bs[1][1][1][0], Bs[1][1][1][1]);   // s1 HxM g1
            MMA(D[mb][0], AM1, Bs[1][0][0][0], Bs[1][0][0][1]);   // s1 MxH g0
            MMA(D[mb][1], AM1, Bs[1][0][1][0], Bs[1][0][1][1]);   // s1 MxH g1
        }
    }

    // All warps must be done reading the smem ring before slog overwrites it.
    __syncthreads();

    // ---- epilogue: stage logits in smem ----
    float* slog = (float*)smem;   // pitch 65 floats per token
#pragma unroll
    for (int mb = 0; mb < 4; mb++) {
        int e0 = mb * 16 + (l >> 2);
        int e1 = e0 + 8;
#pragma unroll
        for (int g = 0; g < 2; g++) {
            int tk = w * 16 + g * 8 + 2 * q;
            slog[(size_t)tk * 65 + e0]       = D[mb][g][0];
            slog[(size_t)(tk + 1) * 65 + e0] = D[mb][g][1];
            slog[(size_t)tk * 65 + e1]       = D[mb][g][2];
            slog[(size_t)(tk + 1) * 65 + e1] = D[mb][g][3];
        }
    }
    __syncthreads();

    if (tid < MTILE) {
        const float* row = slog + (size_t)tid * 65;
        float m1 = -3.4e38f, m2 = -3.4e38f, m3 = -3.4e38f;
        int i1 = 0, i2 = 0;
        float lg[NEXP];
#pragma unroll
        for (int e = 0; e < NEXP; e++) {
            float vv = row[e] + bias[e];
            lg[e] = vv;
            if (vv > m1)      { m3 = m2; m2 = m1; i2 = i1; m1 = vv; i1 = e; }
            else if (vv > m2) { m3 = m2; m2 = vv; i2 = e; }
            else if (vv > m3) { m3 = vv; }
        }
        float s = 0.0f;
#pragma unroll
        for (int e = 0; e < NEXP; e++) s += __expf(lg[e] - m1);

        const float v1 = 1.0f / s;
        const float v2 = __expf(m2 - m1) * v1;
        const int token = blockIdx.x * MTILE + tid;
        ((float2*)out)[token] = make_float2(v1, v2);
        ((float2*)(out + 2 * NTOK))[token] = make_float2((float)i1, (float)i2);

        if ((m1 - m2) < GAP_THR || (m2 - m3) < GAP_THR) {
            int slot = atomicAdd(&g_flag_count, 1);
            if (slot < NTOK) g_flag_tokens[slot] = token;
        }
    }
}

// ---------------------------------------------------------------------------
// Fixup: exact fp32 recompute of flagged tokens (warp-per-8-experts, shuffle
// reduction; W stays L2-hot).
// ---------------------------------------------------------------------------
__global__ __launch_bounds__(256, 1)
void fixup_kernel(const float* __restrict__ x,
                  const float* __restrict__ W,
                  const float* __restrict__ bias,
                  float* __restrict__ out) {
    __shared__ float xs[HIDDEN];
    __shared__ float lg[NEXP];
    const int tid = threadIdx.x;
    const int w = tid >> 5, l = tid & 31;
    const int cnt = min(g_flag_count, NTOK);

    for (int i = blockIdx.x; i < cnt; i += gridDim.x) {
        const int tok = g_flag_tokens[i];
        __syncthreads();
        for (int j = tid; j < HIDDEN / 4; j += 256)
            ((float4*)xs)[j] = ((const float4*)(x + (size_t)tok * HIDDEN))[j];
        __syncthreads();

#pragma unroll
        for (int e8 = 0; e8 < 8; e8++) {
            const int e = w * 8 + e8;
            const float* wr = W + (size_t)e * HIDDEN;
            float s = 0.0f;
#pragma unroll 8
            for (int k = l * 4; k < HIDDEN; k += 128) {
                float4 a = *(const float4*)(xs + k);
                float4 bb = *(const float4*)(wr + k);
                s += a.x * bb.x + a.y * bb.y + a.z * bb.z + a.w * bb.w;
            }
#pragma unroll
            for (int o = 16; o; o >>= 1) s += __shfl_xor_sync(0xFFFFFFFFu, s, o);
            if (l == 0) lg[e] = s + bias[e];
        }
        __syncthreads();

        if (tid == 0) {
            float m1 = -3.4e38f, m2 = -3.4e38f;
            int i1 = 0, i2 = 0;
            for (int ee = 0; ee < NEXP; ee++) {
                float vv = lg[ee];
                if (vv > m1)      { m2 = m1; i2 = i1; m1 = vv; i1 = ee; }
                else if (vv > m2) { m2 = vv; i2 = ee; }
            }
            float ssum = 0.0f;
            for (int ee = 0; ee < NEXP; ee++) ssum += __expf(lg[ee] - m1);
            const float v1 = 1.0f / ssum;
            const float v2 = __expf(m2 - m1) * v1;
            ((float2*)out)[tok] = make_float2(v1, v2);
            ((float2*)(out + 2 * NTOK))[tok] = make_float2((float)i1, (float)i2);
        }
    }
}

// ---------------------------------------------------------------------------
extern "C" void kernel_launch(void* const* d_in, const int* in_sizes, int n_in,
                              void* d_out, int out_size) {
    const float* x = (const float*)d_in[0];
    const float* W = (const float*)d_in[1];
    const float* b = (const float*)d_in[2];
    float* out = (float*)d_out;

    cudaFuncSetAttribute(gating_kernel, cudaFuncAttributeMaxDynamicSharedMemorySize,
                         SMEM_TOTAL);

    prep_w_kernel<<<(NSTEP * FRAG_PER_STEP + 255) / 256, 256>>>(W);
    gating_kernel<<<NCTA, THREADS, SMEM_TOTAL>>>(x, b, out);
    fixup_kernel<<<128, 256>>>(x, W, b, out);
}

// round 10
// speedup vs baseline: 1.8900x; 1.1087x over previous
#include <cuda_runtime.h>
#include <cuda_fp16.h>
#include <cstdint>

// ---------------------------------------------------------------------------
// GatingNetwork: logits = x @ W^T + b ; softmax ; top-2 (values, indices)
// Single-product fp16 HMMA (m16n8k16.f16, fp32 accum). W pre-scaled x256
// (exact), logit = D/256 + b. Logit error sigma ~8e-5; tokens with any top-3
// gap < 8e-4 recomputed exactly in fp32 by the fixup kernel.
// K within each 16-block is permuted (baked into A by prep) so each lane's
// B fragment is one float4 load: slots (2q,2q+1)->(4q,4q+1), (2q+8,+9)->(4q+2,+3).
// One iteration = k64: 32 HMMA per warp (64/SMSP), overhead amortized.
// ---------------------------------------------------------------------------

#define HIDDEN   4096
#define NEXP     64
#define NTOK     16384
#define MTILE    128
#define NCTA     (NTOK / MTILE)        // 128
#define THREADS  256
#define NSTEP    (HIDDEN / 16)         // 256 k16-steps
#define NITER    (NSTEP / 4)           // 64 k64-iterations
#define STEPS_PER_CHUNK 8              // K=128 per W chunk
#define ITERS_PER_CHUNK 2
#define NCHUNK   (NSTEP / STEPS_PER_CHUNK)  // 32
#define GAP_THR  8e-4f
#define WSCALE   256.0f
#define INV_WS   (1.0f / 256.0f)

// per k16 step: 4 mblocks x 32 lanes x uint4 (fp16, single image)
#define FRAG_PER_STEP   (4 * 32)               // 128 uint4 = 2 KB
#define STEP_BYTES      (FRAG_PER_STEP * 16)   // 2048
#define CHUNK_BYTES     (STEPS_PER_CHUNK * STEP_BYTES)  // 16384
#define SMEM_TOTAL      (3 * CHUNK_BYTES)      // 49152

__device__ uint4 g_Wfrag[NSTEP * FRAG_PER_STEP];   // 512 KB
__device__ int   g_flag_count;
__device__ int   g_flag_tokens[NTOK];

static __device__ __forceinline__ uint32_t s2u(const void* p) {
    uint32_t a;
    asm("{ .reg .u64 t; cvta.to.shared.u64 t, %1; cvt.u32.u64 %0, t; }" : "=r"(a) : "l"(p));
    return a;
}

// pack f16x2: hi = f16(f_odd), lo = f16(f_even)
static __device__ __forceinline__ uint32_t pack2h(float f_even, float f_odd) {
    uint32_t r;
    asm("cvt.rn.f16x2.f32 %0, %1, %2;" : "=r"(r) : "f"(f_odd), "f"(f_even));
    return r;
}

#define MMA(D, A, B0, B1)                                                     \
    asm volatile(                                                             \
        "mma.sync.aligned.m16n8k16.row.col.f32.f16.f16.f32 "                  \
        "{%0,%1,%2,%3},{%4,%5,%6,%7},{%8,%9},{%0,%1,%2,%3};"                  \
        : "+f"((D)[0]), "+f"((D)[1]), "+f"((D)[2]), "+f"((D)[3])              \
        : "r"((A)[0]), "r"((A)[1]), "r"((A)[2]), "r"((A)[3]), "r"(B0), "r"(B1))

#define LDS128(R, addr)                                                       \
    asm volatile("ld.shared.v4.b32 {%0,%1,%2,%3}, [%4];"                      \
                 : "=r"((R)[0]), "=r"((R)[1]), "=r"((R)[2]), "=r"((R)[3])     \
                 : "r"(addr))

static __device__ __forceinline__ void cp16(uint32_t sdst, const void* gsrc) {
    asm volatile("cp.async.cg.shared.global [%0], [%1], 16;"
                 :: "r"(sdst), "l"(gsrc) : "memory");
}

// ---------------------------------------------------------------------------
// Prep: W * 256 -> fp16 fragments with the permuted-K layout.
// idx = (t*4 + mb)*32 + lane.
//   v.x = (w[r0][4q],   w[r0][4q+1])   (mma slots 2q,2q+1)
//   v.y = (w[r1][4q],   w[r1][4q+1])
//   v.z = (w[r0][4q+2], w[r0][4q+3])   (mma slots 2q+8,2q+9)
//   v.w = (w[r1][4q+2], w[r1][4q+3])
// ---------------------------------------------------------------------------
__global__ void prep_w_kernel(const float* __restrict__ W) {
    int idx = blockIdx.x * blockDim.x + threadIdx.x;
    if (idx == 0) g_flag_count = 0;
    if (idx >= NSTEP * FRAG_PER_STEP) return;
    int l = idx & 31;
    int r = idx >> 5;
    int mb = r & 3;
    int t = r >> 2;

    int q = l & 3;
    int row0 = mb * 16 + (l >> 2);
    int row1 = row0 + 8;
    int c = t * 16 + 4 * q;

    const float* w0 = W + (size_t)row0 * HIDDEN + c;
    const float* w1 = W + (size_t)row1 * HIDDEN + c;

    uint4 v;
    v.x = pack2h(w0[0] * WSCALE, w0[1] * WSCALE);
    v.y = pack2h(w1[0] * WSCALE, w1[1] * WSCALE);
    v.z = pack2h(w0[2] * WSCALE, w0[3] * WSCALE);
    v.w = pack2h(w1[2] * WSCALE, w1[3] * WSCALE);
    g_Wfrag[idx] = v;
}

// ---------------------------------------------------------------------------
// Main kernel: 8 warps; warp w owns tokens [blk*128 + w*16, +16) x 64 experts.
// One iteration = 4 k16-steps = 32 HMMA per warp.
// ---------------------------------------------------------------------------
__global__ __launch_bounds__(THREADS, 1)
void gating_kernel(const float* __restrict__ x,
                   const float* __restrict__ bias,
                   float* __restrict__ out) {
    extern __shared__ char smem[];
    const uint32_t sb = s2u(smem);
    const int tid = threadIdx.x;
    const int w   = tid >> 5;
    const int l   = tid & 31;
    const int q   = l & 3;

    auto issue_chunk = [&](int ch) {
        const char* gsrc = (const char*)g_Wfrag + (size_t)ch * CHUNK_BYTES;
        uint32_t sdst = sb + (ch % 3) * CHUNK_BYTES;
#pragma unroll
        for (int i = 0; i < CHUNK_BYTES / 16 / THREADS; i++) {
            int off = (tid + i * THREADS) * 16;
            cp16(sdst + off, gsrc + off);
        }
        asm volatile("cp.async.commit_group;" ::: "memory");
    };

    issue_chunk(0);
    issue_chunk(1);

    // lane's x rows: token tbase + l/4 (g1: +8); within k16-step: float4 at 4q
    const int tbase = blockIdx.x * MTILE + w * 16;
    const float* p0 = x + (size_t)(tbase + (l >> 2)) * HIDDEN + 4 * q;
    const float* p1 = p0 + (size_t)8 * HIDDEN;

    // x pipeline: [slot][substep][g] float4 (one iter = 4 substeps = k64)
    float4 vx[2][4][2];
#pragma unroll
    for (int d = 0; d < 2; d++)
#pragma unroll
        for (int su = 0; su < 4; su++) {
            vx[d][su][0] = *(const float4*)(p0 + (size_t)(4 * d + su) * 16);
            vx[d][su][1] = *(const float4*)(p1 + (size_t)(4 * d + su) * 16);
        }

    float D[4][2][4];
#pragma unroll
    for (int mb = 0; mb < 4; mb++)
#pragma unroll
        for (int g = 0; g < 2; g++)
#pragma unroll
            for (int i = 0; i < 4; i++) D[mb][g][i] = 0.0f;

#pragma unroll 1
    for (int it = 0; it < NITER; it++) {
        if ((it & (ITERS_PER_CHUNK - 1)) == 0) {
            const int ch = it / ITERS_PER_CHUNK;
            if (ch < NCHUNK - 1)
                asm volatile("cp.async.wait_group 1;" ::: "memory");
            else
                asm volatile("cp.async.wait_group 0;" ::: "memory");
            __syncthreads();
            if (ch + 2 < NCHUNK) issue_chunk(ch + 2);
        }

        const int slot = it & 1;

        // ---- B fragments: Bs[substep][g][2] straight from float4 ----
        uint32_t Bs[4][2][2];
#pragma unroll
        for (int su = 0; su < 4; su++)
#pragma unroll
            for (int g = 0; g < 2; g++) {
                float4 f = vx[slot][su][g];
                Bs[su][g][0] = pack2h(f.x, f.y);   // slots 2q,2q+1  <- k 4q,4q+1
                Bs[su][g][1] = pack2h(f.z, f.w);   // slots 2q+8,+9  <- k 4q+2,4q+3
            }

        // ---- prefetch x for iteration it+2 into this slot ----
        if (it + 2 < NITER) {
#pragma unroll
            for (int su = 0; su < 4; su++) {
                vx[slot][su][0] = *(const float4*)(p0 + (size_t)(4 * (it + 2) + su) * 16);
                vx[slot][su][1] = *(const float4*)(p1 + (size_t)(4 * (it + 2) + su) * 16);
            }
        }

        // ---- 32 HMMA: 4 substeps x 4 mblocks x {g0, g1} ----
        const uint32_t base = sb + ((it / ITERS_PER_CHUNK) % 3) * CHUNK_BYTES
                              + (it & (ITERS_PER_CHUNK - 1)) * 4 * STEP_BYTES
                              + l * 16;
#pragma unroll
        for (int su = 0; su < 4; su++) {
#pragma unroll
            for (int mb = 0; mb < 4; mb++) {
                uint32_t A[4];
                LDS128(A, base + su * STEP_BYTES + mb * 512);
                MMA(D[mb][0], A, Bs[su][0][0], Bs[su][0][1]);
                MMA(D[mb][1], A, Bs[su][1][0], Bs[su][1][1]);
            }
        }
    }

    // All warps must be done reading the smem ring before slog overwrites it.
    __syncthreads();

    // ---- epilogue: stage logits in smem ----
    float* slog = (float*)smem;   // pitch 65 floats per token
#pragma unroll
    for (int mb = 0; mb < 4; mb++) {
        int e0 = mb * 16 + (l >> 2);
        int e1 = e0 + 8;
#pragma unroll
        for (int g = 0; g < 2; g++) {
            int tk = w * 16 + g * 8 + 2 * q;
            slog[(size_t)tk * 65 + e0]       = D[mb][g][0] * INV_WS;
            slog[(size_t)(tk + 1) * 65 + e0] = D[mb][g][1] * INV_WS;
            slog[(size_t)tk * 65 + e1]       = D[mb][g][2] * INV_WS;
            slog[(size_t)(tk + 1) * 65 + e1] = D[mb][g][3] * INV_WS;
        }
    }
    __syncthreads();

    if (tid < MTILE) {
        const float* row = slog + (size_t)tid * 65;
        float m1 = -3.4e38f, m2 = -3.4e38f, m3 = -3.4e38f;
        int i1 = 0, i2 = 0;
        float lg[NEXP];
#pragma unroll
        for (int e = 0; e < NEXP; e++) {
            float vv = row[e] + bias[e];
            lg[e] = vv;
            if (vv > m1)      { m3 = m2; m2 = m1; i2 = i1; m1 = vv; i1 = e; }
            else if (vv > m2) { m3 = m2; m2 = vv; i2 = e; }
            else if (vv > m3) { m3 = vv; }
        }
        float s = 0.0f;
#pragma unroll
        for (int e = 0; e < NEXP; e++) s += __expf(lg[e] - m1);

        const float v1 = 1.0f / s;
        const float v2 = __expf(m2 - m1) * v1;
        const int token = blockIdx.x * MTILE + tid;
        ((float2*)out)[token] = make_float2(v1, v2);
        ((float2*)(out + 2 * NTOK))[token] = make_float2((float)i1, (float)i2);

        if ((m1 - m2) < GAP_THR || (m2 - m3) < GAP_THR) {
            int slot = atomicAdd(&g_flag_count, 1);
            if (slot < NTOK) g_flag_tokens[slot] = token;
        }
    }
}

// ---------------------------------------------------------------------------
// Fixup: exact fp32 recompute of flagged tokens (warp-per-8-experts, shuffle
// reduction; W stays L2-hot).
// ---------------------------------------------------------------------------
__global__ __launch_bounds__(256, 1)
void fixup_kernel(const float* __restrict__ x,
                  const float* __restrict__ W,
                  const float* __restrict__ bias,
                  float* __restrict__ out) {
    __shared__ float xs[HIDDEN];
    __shared__ float lg[NEXP];
    const int tid = threadIdx.x;
    const int w = tid >> 5, l = tid & 31;
    const int cnt = min(g_flag_count, NTOK);

    for (int i = blockIdx.x; i < cnt; i += gridDim.x) {
        const int tok = g_flag_tokens[i];
        __syncthreads();
        for (int j = tid; j < HIDDEN / 4; j += 256)
            ((float4*)xs)[j] = ((const float4*)(x + (size_t)tok * HIDDEN))[j];
        __syncthreads();

#pragma unroll
        for (int e8 = 0; e8 < 8; e8++) {
            const int e = w * 8 + e8;
            const float* wr = W + (size_t)e * HIDDEN;
            float s = 0.0f;
#pragma unroll 8
            for (int k = l * 4; k < HIDDEN; k += 128) {
                float4 a = *(const float4*)(xs + k);
                float4 bb = *(const float4*)(wr + k);
                s += a.x * bb.x + a.y * bb.y + a.z * bb.z + a.w * bb.w;
            }
#pragma unroll
            for (int o = 16; o; o >>= 1) s += __shfl_xor_sync(0xFFFFFFFFu, s, o);
            if (l == 0) lg[e] = s + bias[e];
        }
        __syncthreads();

        if (tid == 0) {
            float m1 = -3.4e38f, m2 = -3.4e38f;
            int i1 = 0, i2 = 0;
            for (int ee = 0; ee < NEXP; ee++) {
                float vv = lg[ee];
                if (vv > m1)      { m2 = m1; i2 = i1; m1 = vv; i1 = ee; }
                else if (vv > m2) { m2 = vv; i2 = ee; }
            }
            float ssum = 0.0f;
            for (int ee = 0; ee < NEXP; ee++) ssum += __expf(lg[ee] - m1);
            const float v1 = 1.0f / ssum;
            const float v2 = __expf(m2 - m1) * v1;
            ((float2*)out)[tok] = make_float2(v1, v2);
            ((float2*)(out + 2 * NTOK))[tok] = make_float2((float)i1, (float)i2);
        }
        __syncthreads();
    }
}

// ---------------------------------------------------------------------------
extern "C" void kernel_launch(void* const* d_in, const int* in_sizes, int n_in,
                              void* d_out, int out_size) {
    const float* x = (const float*)d_in[0];
    const float* W = (const float*)d_in[1];
    const float* b = (const float*)d_in[2];
    float* out = (float*)d_out;

    cudaFuncSetAttribute(gating_kernel, cudaFuncAttributeMaxDynamicSharedMemorySize,
                         SMEM_TOTAL);

    prep_w_kernel<<<(NSTEP * FRAG_PER_STEP + 255) / 256, 256>>>(W);
    gating_kernel<<<NCTA, THREADS, SMEM_TOTAL>>>(x, b, out);
    fixup_kernel<<<128, 256>>>(x, W, b, out);
}

// round 11
// speedup vs baseline: 2.8596x; 1.5131x over previous
#include <cuda_runtime.h>
#include <cuda_fp16.h>
#include <cstdint>

// ---------------------------------------------------------------------------
// GatingNetwork: logits = x @ W^T + b ; softmax ; top-2 (values, indices)
// Single-product fp16 HMMA (m16n8k16.f16, fp32 accum). W pre-scaled x256
// (exact), logit = D/256 + b. Logit error sigma ~1.4e-4; tokens with any
// top-3 gap < 8e-4 recomputed exactly in fp32 by the fixup kernel.
// Main loop iterates over k128 chunks: 64 HMMA per warp between loop
// boundaries (per-iteration fixed overhead amortized over a long MMA stream).
// ---------------------------------------------------------------------------

#define HIDDEN   4096
#define NEXP     64
#define NTOK     16384
#define MTILE    128
#define NCTA     (NTOK / MTILE)        // 128
#define THREADS  256
#define NSTEP    (HIDDEN / 16)         // 256 k16-steps
#define NHALF    (NSTEP / 4)           // 64 k64-halves
#define STEPS_PER_CHUNK 8              // K=128 per W chunk
#define NCHUNK   (NSTEP / STEPS_PER_CHUNK)  // 32
#define GAP_THR  8e-4f
#define WSCALE   256.0f
#define INV_WS   (1.0f / 256.0f)

// per k16 step: 4 mblocks x 32 lanes x uint4 (fp16, single image)
#define FRAG_PER_STEP   (4 * 32)               // 128 uint4 = 2 KB
#define STEP_BYTES      (FRAG_PER_STEP * 16)   // 2048
#define CHUNK_BYTES     (STEPS_PER_CHUNK * STEP_BYTES)  // 16384
#define SMEM_TOTAL      (3 * CHUNK_BYTES)      // 49152

__device__ uint4 g_Wfrag[NSTEP * FRAG_PER_STEP];   // 512 KB
__device__ int   g_flag_count;
__device__ int   g_flag_tokens[NTOK];

static __device__ __forceinline__ uint32_t s2u(const void* p) {
    uint32_t a;
    asm("{ .reg .u64 t; cvta.to.shared.u64 t, %1; cvt.u32.u64 %0, t; }" : "=r"(a) : "l"(p));
    return a;
}

// pack f16x2: hi = f16(f_odd), lo = f16(f_even)
static __device__ __forceinline__ uint32_t pack2h(float f_even, float f_odd) {
    uint32_t r;
    asm("cvt.rn.f16x2.f32 %0, %1, %2;" : "=r"(r) : "f"(f_odd), "f"(f_even));
    return r;
}

#define MMA(D, A, B0, B1)                                                     \
    asm volatile(                                                             \
        "mma.sync.aligned.m16n8k16.row.col.f32.f16.f16.f32 "                  \
        "{%0,%1,%2,%3},{%4,%5,%6,%7},{%8,%9},{%0,%1,%2,%3};"                  \
        : "+f"((D)[0]), "+f"((D)[1]), "+f"((D)[2]), "+f"((D)[3])              \
        : "r"((A)[0]), "r"((A)[1]), "r"((A)[2]), "r"((A)[3]), "r"(B0), "r"(B1))

#define LDS128(R, addr)                                                       \
    asm volatile("ld.shared.v4.b32 {%0,%1,%2,%3}, [%4];"                      \
                 : "=r"((R)[0]), "=r"((R)[1]), "=r"((R)[2]), "=r"((R)[3])     \
                 : "r"(addr))

static __device__ __forceinline__ void cp16(uint32_t sdst, const void* gsrc) {
    asm volatile("cp.async.cg.shared.global [%0], [%1], 16;"
                 :: "r"(sdst), "l"(gsrc) : "memory");
}

// ---------------------------------------------------------------------------
// Prep: W * 256 -> fp16 fragments with the permuted-K layout.
// idx = (t*4 + mb)*32 + lane.
// ---------------------------------------------------------------------------
__global__ void prep_w_kernel(const float* __restrict__ W) {
    int idx = blockIdx.x * blockDim.x + threadIdx.x;
    if (idx == 0) g_flag_count = 0;
    if (idx >= NSTEP * FRAG_PER_STEP) return;
    int l = idx & 31;
    int r = idx >> 5;
    int mb = r & 3;
    int t = r >> 2;

    int q = l & 3;
    int row0 = mb * 16 + (l >> 2);
    int row1 = row0 + 8;
    int c = t * 16 + 4 * q;

    const float* w0 = W + (size_t)row0 * HIDDEN + c;
    const float* w1 = W + (size_t)row1 * HIDDEN + c;

    uint4 v;
    v.x = pack2h(w0[0] * WSCALE, w0[1] * WSCALE);
    v.y = pack2h(w1[0] * WSCALE, w1[1] * WSCALE);
    v.z = pack2h(w0[2] * WSCALE, w0[3] * WSCALE);
    v.w = pack2h(w1[2] * WSCALE, w1[3] * WSCALE);
    g_Wfrag[idx] = v;
}

// ---------------------------------------------------------------------------
// Main kernel: 8 warps; warp w owns tokens [blk*128 + w*16, +16) x 64 experts.
// One loop iteration = one k128 chunk = 64 HMMA per warp (2 k64 halves).
// ---------------------------------------------------------------------------
__global__ __launch_bounds__(THREADS, 1)
void gating_kernel(const float* __restrict__ x,
                   const float* __restrict__ bias,
                   float* __restrict__ out) {
    extern __shared__ char smem[];
    const uint32_t sb = s2u(smem);
    const int tid = threadIdx.x;
    const int w   = tid >> 5;
    const int l   = tid & 31;
    const int q   = l & 3;

    auto issue_chunk = [&](int ch) {
        const char* gsrc = (const char*)g_Wfrag + (size_t)ch * CHUNK_BYTES;
        uint32_t sdst = sb + (ch % 3) * CHUNK_BYTES;
#pragma unroll
        for (int i = 0; i < CHUNK_BYTES / 16 / THREADS; i++) {
            int off = (tid + i * THREADS) * 16;
            cp16(sdst + off, gsrc + off);
        }
        asm volatile("cp.async.commit_group;" ::: "memory");
    };

    issue_chunk(0);
    issue_chunk(1);

    // lane's x rows: token tbase + l/4 (g1: +8); within k16-step: float4 at 4q
    const int tbase = blockIdx.x * MTILE + w * 16;
    const float* p0 = x + (size_t)(tbase + (l >> 2)) * HIDDEN + 4 * q;
    const float* p1 = p0 + (size_t)8 * HIDDEN;

    // x pipeline: [slot][substep][g] float4, slot = k64-half parity
    float4 vx[2][4][2];
#pragma unroll
    for (int d = 0; d < 2; d++)
#pragma unroll
        for (int su = 0; su < 4; su++) {
            vx[d][su][0] = *(const float4*)(p0 + (size_t)(4 * d + su) * 16);
            vx[d][su][1] = *(const float4*)(p1 + (size_t)(4 * d + su) * 16);
        }

    float D[4][2][4];
#pragma unroll
    for (int mb = 0; mb < 4; mb++)
#pragma unroll
        for (int g = 0; g < 2; g++)
#pragma unroll
            for (int i = 0; i < 4; i++) D[mb][g][i] = 0.0f;

#pragma unroll 1
    for (int ch = 0; ch < NCHUNK; ch++) {
        if (ch < NCHUNK - 1)
            asm volatile("cp.async.wait_group 1;" ::: "memory");
        else
            asm volatile("cp.async.wait_group 0;" ::: "memory");
        __syncthreads();
        if (ch + 2 < NCHUNK) issue_chunk(ch + 2);

        const uint32_t cbase = sb + (ch % 3) * CHUNK_BYTES + l * 16;

        // ---- two k64 halves, fully unrolled: 64 HMMA between boundaries ----
#pragma unroll
        for (int half = 0; half < 2; half++) {
            const int hidx = 2 * ch + half;     // global k64-half index
            const int slot = hidx & 1;

            // B fragments: Bs[substep][g][2] straight from float4
            uint32_t Bs[4][2][2];
#pragma unroll
            for (int su = 0; su < 4; su++)
#pragma unroll
                for (int g = 0; g < 2; g++) {
                    float4 f = vx[slot][su][g];
                    Bs[su][g][0] = pack2h(f.x, f.y);   // slots 2q,2q+1
                    Bs[su][g][1] = pack2h(f.z, f.w);   // slots 2q+8,2q+9
                }

            // prefetch x for half hidx+2 into this slot
            if (hidx + 2 < NHALF) {
#pragma unroll
                for (int su = 0; su < 4; su++) {
                    vx[slot][su][0] = *(const float4*)(p0 + (size_t)(4 * (hidx + 2) + su) * 16);
                    vx[slot][su][1] = *(const float4*)(p1 + (size_t)(4 * (hidx + 2) + su) * 16);
                }
            }

            // 32 HMMA: 4 substeps x 4 mblocks x {g0, g1}
            const uint32_t hbase = cbase + half * 4 * STEP_BYTES;
#pragma unroll
            for (int su = 0; su < 4; su++) {
#pragma unroll
                for (int mb = 0; mb < 4; mb++) {
                    uint32_t A[4];
                    LDS128(A, hbase + su * STEP_BYTES + mb * 512);
                    MMA(D[mb][0], A, Bs[su][0][0], Bs[su][0][1]);
                    MMA(D[mb][1], A, Bs[su][1][0], Bs[su][1][1]);
                }
            }
        }
    }

    // All warps must be done reading the smem ring before slog overwrites it.
    __syncthreads();

    // ---- epilogue: stage logits in smem ----
    float* slog = (float*)smem;   // pitch 65 floats per token
#pragma unroll
    for (int mb = 0; mb < 4; mb++) {
        int e0 = mb * 16 + (l >> 2);
        int e1 = e0 + 8;
#pragma unroll
        for (int g = 0; g < 2; g++) {
            int tk = w * 16 + g * 8 + 2 * q;
            slog[(size_t)tk * 65 + e0]       = D[mb][g][0] * INV_WS;
            slog[(size_t)(tk + 1) * 65 + e0] = D[mb][g][1] * INV_WS;
            slog[(size_t)tk * 65 + e1]       = D[mb][g][2] * INV_WS;
            slog[(size_t)(tk + 1) * 65 + e1] = D[mb][g][3] * INV_WS;
        }
    }
    __syncthreads();

    if (tid < MTILE) {
        const float* row = slog + (size_t)tid * 65;
        float m1 = -3.4e38f, m2 = -3.4e38f, m3 = -3.4e38f;
        int i1 = 0, i2 = 0;
        float lg[NEXP];
#pragma unroll
        for (int e = 0; e < NEXP; e++) {
            float vv = row[e] + bias[e];
            lg[e] = vv;
            if (vv > m1)      { m3 = m2; m2 = m1; i2 = i1; m1 = vv; i1 = e; }
            else if (vv > m2) { m3 = m2; m2 = vv; i2 = e; }
            else if (vv > m3) { m3 = vv; }
        }
        float s = 0.0f;
#pragma unroll
        for (int e = 0; e < NEXP; e++) s += __expf(lg[e] - m1);

        const float v1 = 1.0f / s;
        const float v2 = __expf(m2 - m1) * v1;
        const int token = blockIdx.x * MTILE + tid;
        ((float2*)out)[token] = make_float2(v1, v2);
        ((float2*)(out + 2 * NTOK))[token] = make_float2((float)i1, (float)i2);

        if ((m1 - m2) < GAP_THR || (m2 - m3) < GAP_THR) {
            int slot = atomicAdd(&g_flag_count, 1);
            if (slot < NTOK) g_flag_tokens[slot] = token;
        }
    }
}

// ---------------------------------------------------------------------------
// Fixup: exact fp32 recompute of flagged tokens (warp-per-8-experts, shuffle
// reduction; W stays L2-hot).
// ---------------------------------------------------------------------------
__global__ __launch_bounds__(256, 1)
void fixup_kernel(const float* __restrict__ x,
                  const float* __restrict__ W,
                  const float* __restrict__ bias,
                  float* __restrict__ out) {
    __shared__ float xs[HIDDEN];
    __shared__ float lg[NEXP];
    const int tid = threadIdx.x;
    const int w = tid >> 5, l = tid & 31;
    const int cnt = min(g_flag_count, NTOK);

    for (int i = blockIdx.x; i < cnt; i += gridDim.x) {
        const int tok = g_flag_tokens[i];
        __syncthreads();
        for (int j = tid; j < HIDDEN / 4; j += 256)
            ((float4*)xs)[j] = ((const float4*)(x + (size_t)tok * HIDDEN))[j];
        __syncthreads();

#pragma unroll
        for (int e8 = 0; e8 < 8; e8++) {
            const int e = w * 8 + e8;
            const float* wr = W + (size_t)e * HIDDEN;
            float s = 0.0f;
#pragma unroll 8
            for (int k = l * 4; k < HIDDEN; k += 128) {
                float4 a = *(const float4*)(xs + k);
                float4 bb = *(const float4*)(wr + k);
                s += a.x * bb.x + a.y * bb.y + a.z * bb.z + a.w * bb.w;
            }
#pragma unroll
            for (int o = 16; o; o >>= 1) s += __shfl_xor_sync(0xFFFFFFFFu, s, o);
            if (l == 0) lg[e] = s + bias[e];
        }
        __syncthreads();

        if (tid == 0) {
            float m1 = -3.4e38f, m2 = -3.4e38f;
            int i1 = 0, i2 = 0;
            for (int ee = 0; ee < NEXP; ee++) {
                float vv = lg[ee];
                if (vv > m1)      { m2 = m1; i2 = i1; m1 = vv; i1 = ee; }
                else if (vv > m2) { m2 = vv; i2 = ee; }
            }
            float ssum = 0.0f;
            for (int ee = 0; ee < NEXP; ee++) ssum += __expf(lg[ee] - m1);
            const float v1 = 1.0f / ssum;
            const float v2 = __expf(m2 - m1) * v1;
            ((float2*)out)[tok] = make_float2(v1, v2);
            ((float2*)(out + 2 * NTOK))[tok] = make_float2((float)i1, (float)i2);
        }
        __syncthreads();
    }
}

// ---------------------------------------------------------------------------
extern "C" void kernel_launch(void* const* d_in, const int* in_sizes, int n_in,
                              void* d_out, int out_size) {
    const float* x = (const float*)d_in[0];
    const float* W = (const float*)d_in[1];
    const float* b = (const float*)d_in[2];
    float* out = (float*)d_out;

    cudaFuncSetAttribute(gating_kernel, cudaFuncAttributeMaxDynamicSharedMemorySize,
                         SMEM_TOTAL);

    prep_w_kernel<<<(NSTEP * FRAG_PER_STEP + 255) / 256, 256>>>(W);
    gating_kernel<<<NCTA, THREADS, SMEM_TOTAL>>>(x, b, out);
    fixup_kernel<<<128, 256>>>(x, W, b, out);
}

// round 12
// speedup vs baseline: 2.9166x; 1.0199x over previous
#include <cuda_runtime.h>
#include <cuda_fp16.h>
#include <cstdint>

// ---------------------------------------------------------------------------
// GatingNetwork: logits = x @ W^T + b ; softmax ; top-2 (values, indices)
// Single-product fp16 HMMA (m16n8k16.f16, fp32 accum). W pre-scaled x256
// (exact), logit = D/256 + b. Logit error sigma ~1.4e-4; tokens with any
// top-3 gap < 8e-4 recomputed exactly in fp32 by the fixup kernel.
// Main loop iterates over k256 chunks: 128 HMMA per warp between loop
// boundaries (per-iteration fixed overhead amortized over a long MMA stream).
// ---------------------------------------------------------------------------

#define HIDDEN   4096
#define NEXP     64
#define NTOK     16384
#define MTILE    128
#define NCTA     (NTOK / MTILE)        // 128
#define THREADS  256
#define NSTEP    (HIDDEN / 16)         // 256 k16-steps
#define NHALF    (NSTEP / 4)           // 64 k64-halves
#define STEPS_PER_CHUNK 16             // K=256 per W chunk
#define HALVES_PER_CHUNK 4
#define NCHUNK   (NSTEP / STEPS_PER_CHUNK)  // 16
#define GAP_THR  8e-4f
#define WSCALE   256.0f
#define INV_WS   (1.0f / 256.0f)

// per k16 step: 4 mblocks x 32 lanes x uint4 (fp16, single image)
#define FRAG_PER_STEP   (4 * 32)               // 128 uint4 = 2 KB
#define STEP_BYTES      (FRAG_PER_STEP * 16)   // 2048
#define CHUNK_BYTES     (STEPS_PER_CHUNK * STEP_BYTES)  // 32768
#define SMEM_TOTAL      (3 * CHUNK_BYTES)      // 98304

__device__ uint4 g_Wfrag[NSTEP * FRAG_PER_STEP];   // 512 KB
__device__ int   g_flag_count;
__device__ int   g_flag_tokens[NTOK];

static __device__ __forceinline__ uint32_t s2u(const void* p) {
    uint32_t a;
    asm("{ .reg .u64 t; cvta.to.shared.u64 t, %1; cvt.u32.u64 %0, t; }" : "=r"(a) : "l"(p));
    return a;
}

// pack f16x2: hi = f16(f_odd), lo = f16(f_even)
static __device__ __forceinline__ uint32_t pack2h(float f_even, float f_odd) {
    uint32_t r;
    asm("cvt.rn.f16x2.f32 %0, %1, %2;" : "=r"(r) : "f"(f_odd), "f"(f_even));
    return r;
}

#define MMA(D, A, B0, B1)                                                     \
    asm volatile(                                                             \
        "mma.sync.aligned.m16n8k16.row.col.f32.f16.f16.f32 "                  \
        "{%0,%1,%2,%3},{%4,%5,%6,%7},{%8,%9},{%0,%1,%2,%3};"                  \
        : "+f"((D)[0]), "+f"((D)[1]), "+f"((D)[2]), "+f"((D)[3])              \
        : "r"((A)[0]), "r"((A)[1]), "r"((A)[2]), "r"((A)[3]), "r"(B0), "r"(B1))

#define LDS128(R, addr)                                                       \
    asm volatile("ld.shared.v4.b32 {%0,%1,%2,%3}, [%4];"                      \
                 : "=r"((R)[0]), "=r"((R)[1]), "=r"((R)[2]), "=r"((R)[3])     \
                 : "r"(addr))

static __device__ __forceinline__ void cp16(uint32_t sdst, const void* gsrc) {
    asm volatile("cp.async.cg.shared.global [%0], [%1], 16;"
                 :: "r"(sdst), "l"(gsrc) : "memory");
}

// ---------------------------------------------------------------------------
// Prep: W * 256 -> fp16 fragments with the permuted-K layout.
// idx = (t*4 + mb)*32 + lane.
// ---------------------------------------------------------------------------
__global__ void prep_w_kernel(const float* __restrict__ W) {
    int idx = blockIdx.x * blockDim.x + threadIdx.x;
    if (idx == 0) g_flag_count = 0;
    if (idx >= NSTEP * FRAG_PER_STEP) return;
    int l = idx & 31;
    int r = idx >> 5;
    int mb = r & 3;
    int t = r >> 2;

    int q = l & 3;
    int row0 = mb * 16 + (l >> 2);
    int row1 = row0 + 8;
    int c = t * 16 + 4 * q;

    const float* w0 = W + (size_t)row0 * HIDDEN + c;
    const float* w1 = W + (size_t)row1 * HIDDEN + c;

    uint4 v;
    v.x = pack2h(w0[0] * WSCALE, w0[1] * WSCALE);
    v.y = pack2h(w1[0] * WSCALE, w1[1] * WSCALE);
    v.z = pack2h(w0[2] * WSCALE, w0[3] * WSCALE);
    v.w = pack2h(w1[2] * WSCALE, w1[3] * WSCALE);
    g_Wfrag[idx] = v;
}

// ---------------------------------------------------------------------------
// Main kernel: 8 warps; warp w owns tokens [blk*128 + w*16, +16) x 64 experts.
// One loop iteration = one k256 chunk = 128 HMMA per warp (4 k64 halves).
// ---------------------------------------------------------------------------
__global__ __launch_bounds__(THREADS, 1)
void gating_kernel(const float* __restrict__ x,
                   const float* __restrict__ bias,
                   float* __restrict__ out) {
    extern __shared__ char smem[];
    const uint32_t sb = s2u(smem);
    const int tid = threadIdx.x;
    const int w   = tid >> 5;
    const int l   = tid & 31;
    const int q   = l & 3;

    auto issue_chunk = [&](int ch) {
        const char* gsrc = (const char*)g_Wfrag + (size_t)ch * CHUNK_BYTES;
        uint32_t sdst = sb + (ch % 3) * CHUNK_BYTES;
#pragma unroll
        for (int i = 0; i < CHUNK_BYTES / 16 / THREADS; i++) {
            int off = (tid + i * THREADS) * 16;
            cp16(sdst + off, gsrc + off);
        }
        asm volatile("cp.async.commit_group;" ::: "memory");
    };

    issue_chunk(0);
    issue_chunk(1);

    // lane's x rows: token tbase + l/4 (g1: +8); within k16-step: float4 at 4q
    const int tbase = blockIdx.x * MTILE + w * 16;
    const float* p0 = x + (size_t)(tbase + (l >> 2)) * HIDDEN + 4 * q;
    const float* p1 = p0 + (size_t)8 * HIDDEN;

    // x pipeline: [slot][substep][g] float4, slot = k64-half parity
    float4 vx[2][4][2];
#pragma unroll
    for (int d = 0; d < 2; d++)
#pragma unroll
        for (int su = 0; su < 4; su++) {
            vx[d][su][0] = *(const float4*)(p0 + (size_t)(4 * d + su) * 16);
            vx[d][su][1] = *(const float4*)(p1 + (size_t)(4 * d + su) * 16);
        }

    float D[4][2][4];
#pragma unroll
    for (int mb = 0; mb < 4; mb++)
#pragma unroll
        for (int g = 0; g < 2; g++)
#pragma unroll
            for (int i = 0; i < 4; i++) D[mb][g][i] = 0.0f;

#pragma unroll 1
    for (int ch = 0; ch < NCHUNK; ch++) {
        if (ch < NCHUNK - 1)
            asm volatile("cp.async.wait_group 1;" ::: "memory");
        else
            asm volatile("cp.async.wait_group 0;" ::: "memory");
        __syncthreads();
        if (ch + 2 < NCHUNK) issue_chunk(ch + 2);

        const uint32_t cbase = sb + (ch % 3) * CHUNK_BYTES + l * 16;

        // ---- four k64 halves, fully unrolled: 128 HMMA between boundaries ----
#pragma unroll
        for (int half = 0; half < HALVES_PER_CHUNK; half++) {
            const int hidx = HALVES_PER_CHUNK * ch + half;  // global k64-half
            const int slot = hidx & 1;

            // B fragments: Bs[substep][g][2] straight from float4
            uint32_t Bs[4][2][2];
#pragma unroll
            for (int su = 0; su < 4; su++)
#pragma unroll
                for (int g = 0; g < 2; g++) {
                    float4 f = vx[slot][su][g];
                    Bs[su][g][0] = pack2h(f.x, f.y);   // slots 2q,2q+1
                    Bs[su][g][1] = pack2h(f.z, f.w);   // slots 2q+8,2q+9
                }

            // prefetch x for half hidx+2 into this slot
            if (hidx + 2 < NHALF) {
#pragma unroll
                for (int su = 0; su < 4; su++) {
                    vx[slot][su][0] = *(const float4*)(p0 + (size_t)(4 * (hidx + 2) + su) * 16);
                    vx[slot][su][1] = *(const float4*)(p1 + (size_t)(4 * (hidx + 2) + su) * 16);
                }
            }

            // 32 HMMA: 4 substeps x 4 mblocks x {g0, g1}
            const uint32_t hbase = cbase + half * 4 * STEP_BYTES;
#pragma unroll
            for (int su = 0; su < 4; su++) {
#pragma unroll
                for (int mb = 0; mb < 4; mb++) {
                    uint32_t A[4];
                    LDS128(A, hbase + su * STEP_BYTES + mb * 512);
                    MMA(D[mb][0], A, Bs[su][0][0], Bs[su][0][1]);
                    MMA(D[mb][1], A, Bs[su][1][0], Bs[su][1][1]);
                }
            }
        }
    }

    // All warps must be done reading the smem ring before slog overwrites it.
    __syncthreads();

    // ---- epilogue: stage logits in smem ----
    float* slog = (float*)smem;   // pitch 65 floats per token
#pragma unroll
    for (int mb = 0; mb < 4; mb++) {
        int e0 = mb * 16 + (l >> 2);
        int e1 = e0 + 8;
#pragma unroll
        for (int g = 0; g < 2; g++) {
            int tk = w * 16 + g * 8 + 2 * q;
            slog[(size_t)tk * 65 + e0]       = D[mb][g][0] * INV_WS;
            slog[(size_t)(tk + 1) * 65 + e0] = D[mb][g][1] * INV_WS;
            slog[(size_t)tk * 65 + e1]       = D[mb][g][2] * INV_WS;
            slog[(size_t)(tk + 1) * 65 + e1] = D[mb][g][3] * INV_WS;
        }
    }
    __syncthreads();

    if (tid < MTILE) {
        const float* row = slog + (size_t)tid * 65;
        float m1 = -3.4e38f, m2 = -3.4e38f, m3 = -3.4e38f;
        int i1 = 0, i2 = 0;
        float lg[NEXP];
#pragma unroll
        for (int e = 0; e < NEXP; e++) {
            float vv = row[e] + bias[e];
            lg[e] = vv;
            if (vv > m1)      { m3 = m2; m2 = m1; i2 = i1; m1 = vv; i1 = e; }
            else if (vv > m2) { m3 = m2; m2 = vv; i2 = e; }
            else if (vv > m3) { m3 = vv; }
        }
        float s = 0.0f;
#pragma unroll
        for (int e = 0; e < NEXP; e++) s += __expf(lg[e] - m1);

        const float v1 = 1.0f / s;
        const float v2 = __expf(m2 - m1) * v1;
        const int token = blockIdx.x * MTILE + tid;
        ((float2*)out)[token] = make_float2(v1, v2);
        ((float2*)(out + 2 * NTOK))[token] = make_float2((float)i1, (float)i2);

        if ((m1 - m2) < GAP_THR || (m2 - m3) < GAP_THR) {
            int slot = atomicAdd(&g_flag_count, 1);
            if (slot < NTOK) g_flag_tokens[slot] = token;
        }
    }
}

// ---------------------------------------------------------------------------
// Fixup: exact fp32 recompute of flagged tokens (warp-per-8-experts, shuffle
// reduction; W stays L2-hot).
// ---------------------------------------------------------------------------
__global__ __launch_bounds__(256, 1)
void fixup_kernel(const float* __restrict__ x,
                  const float* __restrict__ W,
                  const float* __restrict__ bias,
                  float* __restrict__ out) {
    __shared__ float xs[HIDDEN];
    __shared__ float lg[NEXP];
    const int tid = threadIdx.x;
    const int w = tid >> 5, l = tid & 31;
    const int cnt = min(g_flag_count, NTOK);

    for (int i = blockIdx.x; i < cnt; i += gridDim.x) {
        const int tok = g_flag_tokens[i];
        __syncthreads();
        for (int j = tid; j < HIDDEN / 4; j += 256)
            ((float4*)xs)[j] = ((const float4*)(x + (size_t)tok * HIDDEN))[j];
        __syncthreads();

#pragma unroll
        for (int e8 = 0; e8 < 8; e8++) {
            const int e = w * 8 + e8;
            const float* wr = W + (size_t)e * HIDDEN;
            float s = 0.0f;
#pragma unroll 8
            for (int k = l * 4; k < HIDDEN; k += 128) {
                float4 a = *(const float4*)(xs + k);
                float4 bb = *(const float4*)(wr + k);
                s += a.x * bb.x + a.y * bb.y + a.z * bb.z + a.w * bb.w;
            }
#pragma unroll
            for (int o = 16; o; o >>= 1) s += __shfl_xor_sync(0xFFFFFFFFu, s, o);
            if (l == 0) lg[e] = s + bias[e];
        }
        __syncthreads();

        if (tid == 0) {
            float m1 = -3.4e38f, m2 = -3.4e38f;
            int i1 = 0, i2 = 0;
            for (int ee = 0; ee < NEXP; ee++) {
                float vv = lg[ee];
                if (vv > m1)      { m2 = m1; i2 = i1; m1 = vv; i1 = ee; }
                else if (vv > m2) { m2 = vv; i2 = ee; }
            }
            float ssum = 0.0f;
            for (int ee = 0; ee < NEXP; ee++) ssum += __expf(lg[ee] - m1);
            const float v1 = 1.0f / ssum;
            const float v2 = __expf(m2 - m1) * v1;
            ((float2*)out)[tok] = make_float2(v1, v2);
            ((float2*)(out + 2 * NTOK))[tok] = make_float2((float)i1, (float)i2);
        }
        __syncthreads();
    }
}

// ---------------------------------------------------------------------------
extern "C" void kernel_launch(void* const* d_in, const int* in_sizes, int n_in,
                              void* d_out, int out_size) {
    const float* x = (const float*)d_in[0];
    const float* W = (const float*)d_in[1];
    const float* b = (const float*)d_in[2];
    float* out = (float*)d_out;

    cudaFuncSetAttribute(gating_kernel, cudaFuncAttributeMaxDynamicSharedMemorySize,
                         SMEM_TOTAL);

    prep_w_kernel<<<(NSTEP * FRAG_PER_STEP + 255) / 256, 256>>>(W);
    gating_kernel<<<NCTA, THREADS, SMEM_TOTAL>>>(x, b, out);
    fixup_kernel<<<128, 256>>>(x, W, b, out);
}